// round 1
// baseline (speedup 1.0000x reference)
#include <cuda_runtime.h>
#include <cstdint>

#define B 4
#define N 32768
#define PRE 4096
#define POST 512
#define NMS_TH 0.7f

// ---------------- scratch (device globals, no allocation) ----------------
__device__ unsigned long long g_keysA[B * N];
__device__ unsigned long long g_keysB[B * N];
__device__ unsigned char g_labels8[B * N];

__device__ float g_x1[B * PRE], g_y1[B * PRE], g_x2[B * PRE], g_y2[B * PRE], g_area[B * PRE];
__device__ float g_boxes7[B * PRE * 7];
__device__ float g_sc[B * PRE];
__device__ int   g_lb[B * PRE];

// ---------------- kernel 1: score / label / sort key ----------------
__global__ void k_score(const float* __restrict__ cls) {
    int t = blockIdx.x * blockDim.x + threadIdx.x;
    if (t >= B * N) return;
    const float* c = cls + (size_t)t * 3;
    float c0 = c[0], c1 = c[1], c2 = c[2];
    float best = c0; int lab = 0;
    if (c1 > best) { best = c1; lab = 1; }
    if (c2 > best) { best = c2; lab = 2; }
    unsigned int sb = __float_as_uint(best);   // scores are >= 0 -> monotonic bits
    unsigned int n = (unsigned int)(t & (N - 1));
    g_keysA[t] = ((unsigned long long)sb << 32) | (0xFFFFFFFFu - n); // desc key, tie -> smaller n
    g_labels8[t] = (unsigned char)lab;
}

// ---------------- kernel 2: bitonic sort of 4096-key chunks (descending) ----------------
__global__ void k_sort4096() {
    __shared__ unsigned long long s[PRE];
    unsigned long long* g = g_keysA + (size_t)blockIdx.x * PRE;
    for (int i = threadIdx.x; i < PRE; i += blockDim.x) s[i] = g[i];
    __syncthreads();
    for (int k = 2; k <= PRE; k <<= 1) {
        for (int j = k >> 1; j > 0; j >>= 1) {
            for (int i = threadIdx.x; i < PRE / 2; i += blockDim.x) {
                int lo = i & (j - 1);
                int idx = ((i - lo) << 1) | lo;
                int p = idx | j;
                bool descending = ((idx & k) == 0);
                unsigned long long a = s[idx], b = s[p];
                if ((a < b) == descending) { s[idx] = b; s[p] = a; }
            }
            __syncthreads();
        }
    }
    for (int i = threadIdx.x; i < PRE; i += blockDim.x) g[i] = s[i];
}

// ---------------- kernel 3: merge two sorted-desc 4096 lists, keep top 4096 ----------------
__global__ void k_merge(int round) {
    extern __shared__ unsigned long long s[]; // 8192 keys
    const unsigned long long* src;
    unsigned long long* dst;
    int pairs;
    if (round == 0)      { src = g_keysA; dst = g_keysB; pairs = 4; }
    else if (round == 1) { src = g_keysB; dst = g_keysA; pairs = 2; }
    else                 { src = g_keysA; dst = g_keysB; pairs = 1; }
    int batch = blockIdx.x / pairs;
    int pair = blockIdx.x % pairs;
    const unsigned long long* a = src + (size_t)batch * N + (size_t)pair * 2 * PRE;
    for (int i = threadIdx.x; i < PRE; i += blockDim.x) s[i] = a[i];
    for (int i = threadIdx.x; i < PRE; i += blockDim.x) s[2 * PRE - 1 - i] = a[PRE + i]; // reversed -> bitonic
    __syncthreads();
    // stage 1: keep max of (i, i+4096) in low half -> low half is bitonic & contains top 4096
    for (int i = threadIdx.x; i < PRE; i += blockDim.x) {
        unsigned long long x = s[i], y = s[i + PRE];
        s[i] = (x > y) ? x : y;
    }
    __syncthreads();
    // bitonic-merge low half descending
    for (int j = PRE >> 1; j > 0; j >>= 1) {
        for (int i = threadIdx.x; i < PRE / 2; i += blockDim.x) {
            int lo = i & (j - 1);
            int idx = ((i - lo) << 1) | lo;
            int p = idx | j;
            unsigned long long x = s[idx], y = s[p];
            if (x < y) { s[idx] = y; s[p] = x; }
        }
        __syncthreads();
    }
    unsigned long long* d = dst + (size_t)batch * N + (size_t)pair * PRE;
    for (int i = threadIdx.x; i < PRE; i += blockDim.x) d[i] = s[i];
}

// ---------------- kernel 4: gather boxes for top-4096, precompute corners/areas ----------------
__global__ void k_gather(const float* __restrict__ boxes) {
    int t = blockIdx.x * blockDim.x + threadIdx.x;
    if (t >= B * PRE) return;
    int b = t >> 12;
    int r = t & (PRE - 1);
    unsigned long long key = g_keysB[(size_t)b * N + r];
    unsigned int n = 0xFFFFFFFFu - (unsigned int)(key & 0xFFFFFFFFu);
    float sc = __uint_as_float((unsigned int)(key >> 32));
    const float* bx = boxes + ((size_t)b * N + n) * 7;
    float x = bx[0], y = bx[1], z = bx[2], dx = bx[3], dy = bx[4], dz = bx[5], hd = bx[6];
    float* ob = g_boxes7 + (size_t)t * 7;
    ob[0] = x; ob[1] = y; ob[2] = z; ob[3] = dx; ob[4] = dy; ob[5] = dz; ob[6] = hd;
    g_x1[t] = x - 0.5f * dx;
    g_x2[t] = x + 0.5f * dx;
    g_y1[t] = y - 0.5f * dy;
    g_y2[t] = y + 0.5f * dy;
    g_area[t] = dx * dy;
    g_sc[t] = sc;
    g_lb[t] = (int)g_labels8[(size_t)b * N + n];
}

// ---------------- kernel 5: greedy NMS scan, early stop at 512 kept ----------------
#define NMS_THREADS 256
#define NMS_SMEM (5 * PRE * 4 + PRE)

__global__ void k_nms(float* __restrict__ out) {
    extern __shared__ float sm[];
    float* sx1 = sm;
    float* sy1 = sm + PRE;
    float* sx2 = sm + 2 * PRE;
    float* sy2 = sm + 3 * PRE;
    float* sar = sm + 4 * PRE;
    unsigned char* sup = (unsigned char*)(sm + 5 * PRE);
    __shared__ int s_i;

    int b = blockIdx.x;
    int tid = threadIdx.x;
    int base = b * PRE;

    for (int i = tid; i < PRE; i += NMS_THREADS) {
        sx1[i] = g_x1[base + i];
        sy1[i] = g_y1[base + i];
        sx2[i] = g_x2[base + i];
        sy2[i] = g_y2[base + i];
        sar[i] = g_area[base + i];
        sup[i] = 0;
    }
    // output layout: rois [B,512,7] | scores [B,512] | labels [B,512]  (all float32)
    float* rois   = out;
    float* scores = out + B * POST * 7;
    float* labs   = out + B * POST * 7 + B * POST;
    for (int i = tid; i < POST * 7; i += NMS_THREADS) rois[b * POST * 7 + i] = 0.f;
    for (int i = tid; i < POST; i += NMS_THREADS) { scores[b * POST + i] = 0.f; labs[b * POST + i] = 0.f; }
    __syncthreads();

    int kept = 0;
    int cursor = 0;
    while (true) {
        if (tid == 0) {
            int i = cursor;
            while (i < PRE && sup[i]) i++;
            s_i = (i < PRE) ? i : -1;
        }
        __syncthreads();
        int i = s_i;
        if (i < 0) break;
        cursor = i + 1;

        if (tid < 7) rois[(b * POST + kept) * 7 + tid] = g_boxes7[(size_t)(base + i) * 7 + tid];
        if (tid == 7) scores[b * POST + kept] = g_sc[base + i];
        if (tid == 8) labs[b * POST + kept] = (float)(g_lb[base + i] + 1);
        kept++;
        if (kept >= POST) break;   // suppression beyond here cannot affect the first 512 kept

        float xi1 = sx1[i], yi1 = sy1[i], xi2 = sx2[i], yi2 = sy2[i], ai = sar[i];
        for (int j = i + 1 + tid; j < PRE; j += NMS_THREADS) {
            if (!sup[j]) {
                float ix = fminf(xi2, sx2[j]) - fmaxf(xi1, sx1[j]);
                float iy = fminf(yi2, sy2[j]) - fmaxf(yi1, sy1[j]);
                ix = fmaxf(ix, 0.f);
                iy = fmaxf(iy, 0.f);
                float inter = ix * iy;
                float iou = inter / (ai + sar[j] - inter + 1e-6f);
                if (iou > NMS_TH) sup[j] = 1;
            }
        }
        __syncthreads();
    }
}

// ---------------- launch ----------------
extern "C" void kernel_launch(void* const* d_in, const int* in_sizes, int n_in,
                              void* d_out, int out_size) {
    const float* boxes = (const float*)d_in[0];
    const float* cls   = (const float*)d_in[1];
    // robust to input ordering: identify by element count
    if (in_sizes[0] == B * N * 3) {
        cls = (const float*)d_in[0];
        boxes = (const float*)d_in[1];
    }

    cudaFuncSetAttribute(k_merge, cudaFuncAttributeMaxDynamicSharedMemorySize, 2 * PRE * 8);
    cudaFuncSetAttribute(k_nms, cudaFuncAttributeMaxDynamicSharedMemorySize, NMS_SMEM);

    k_score<<<(B * N + 255) / 256, 256>>>(cls);
    k_sort4096<<<B * 8, 512>>>();
    k_merge<<<B * 4, 512, 2 * PRE * 8>>>(0);
    k_merge<<<B * 2, 512, 2 * PRE * 8>>>(1);
    k_merge<<<B * 1, 512, 2 * PRE * 8>>>(2);
    k_gather<<<(B * PRE + 255) / 256, 256>>>(boxes);
    k_nms<<<B, NMS_THREADS, NMS_SMEM>>>((float*)d_out);
}

// round 2
// speedup vs baseline: 7.8980x; 7.8980x over previous
#include <cuda_runtime.h>
#include <cstdint>

#define B 4
#define N 32768
#define PRE 4096
#define POST 512
#define NMS_TH 0.7f
#define M 2048            // mask window (rows & cols of candidate matrix)
#define W (M / 64)        // 32 u64 words per mask row

typedef unsigned long long u64;

// ---------------- scratch (device globals, no allocation) ----------------
__device__ u64 g_keysA[B * N];
__device__ u64 g_keysB[B * N];
__device__ unsigned char g_labels8[B * N];

__device__ float g_x1[B * PRE], g_y1[B * PRE], g_x2[B * PRE], g_y2[B * PRE], g_area[B * PRE];
__device__ float g_boxes7[B * PRE * 7];
__device__ float g_sc[B * PRE];
__device__ int   g_lb[B * PRE];

__device__ u64 g_mask[B * M * W];
__device__ int g_keep[B * POST];
__device__ int g_cnt[B];
__device__ int g_fail[B];

// ---------------- kernel 1: score / label / sort key ----------------
__global__ void k_score(const float* __restrict__ cls) {
    int t = blockIdx.x * blockDim.x + threadIdx.x;
    if (t >= B * N) return;
    const float* c = cls + (size_t)t * 3;
    float c0 = c[0], c1 = c[1], c2 = c[2];
    float best = c0; int lab = 0;
    if (c1 > best) { best = c1; lab = 1; }
    if (c2 > best) { best = c2; lab = 2; }
    unsigned int sb = __float_as_uint(best);   // scores >= 0 -> monotonic bits
    unsigned int n = (unsigned int)(t & (N - 1));
    g_keysA[t] = ((u64)sb << 32) | (0xFFFFFFFFu - n); // desc key, tie -> smaller n
    g_labels8[t] = (unsigned char)lab;
}

// ---------------- kernel 2: bitonic sort of 4096-key chunks (descending) ----------------
__global__ void k_sort4096() {
    __shared__ u64 s[PRE];
    u64* g = g_keysA + (size_t)blockIdx.x * PRE;
    for (int i = threadIdx.x; i < PRE; i += blockDim.x) s[i] = g[i];
    __syncthreads();
    for (int k = 2; k <= PRE; k <<= 1) {
        for (int j = k >> 1; j > 0; j >>= 1) {
            for (int i = threadIdx.x; i < PRE / 2; i += blockDim.x) {
                int lo = i & (j - 1);
                int idx = ((i - lo) << 1) | lo;
                int p = idx | j;
                bool descending = ((idx & k) == 0);
                u64 a = s[idx], b = s[p];
                if ((a < b) == descending) { s[idx] = b; s[p] = a; }
            }
            __syncthreads();
        }
    }
    for (int i = threadIdx.x; i < PRE; i += blockDim.x) g[i] = s[i];
}

// ---------------- kernel 3: merge two sorted-desc 4096 lists, keep top 4096 ----------------
__global__ void k_merge(int round) {
    extern __shared__ u64 s[]; // 8192 keys
    const u64* src;
    u64* dst;
    int pairs;
    if (round == 0)      { src = g_keysA; dst = g_keysB; pairs = 4; }
    else if (round == 1) { src = g_keysB; dst = g_keysA; pairs = 2; }
    else                 { src = g_keysA; dst = g_keysB; pairs = 1; }
    int batch = blockIdx.x / pairs;
    int pair = blockIdx.x % pairs;
    const u64* a = src + (size_t)batch * N + (size_t)pair * 2 * PRE;
    for (int i = threadIdx.x; i < PRE; i += blockDim.x) s[i] = a[i];
    for (int i = threadIdx.x; i < PRE; i += blockDim.x) s[2 * PRE - 1 - i] = a[PRE + i]; // reversed -> bitonic
    __syncthreads();
    for (int i = threadIdx.x; i < PRE; i += blockDim.x) {
        u64 x = s[i], y = s[i + PRE];
        s[i] = (x > y) ? x : y;
    }
    __syncthreads();
    for (int j = PRE >> 1; j > 0; j >>= 1) {
        for (int i = threadIdx.x; i < PRE / 2; i += blockDim.x) {
            int lo = i & (j - 1);
            int idx = ((i - lo) << 1) | lo;
            int p = idx | j;
            u64 x = s[idx], y = s[p];
            if (x < y) { s[idx] = y; s[p] = x; }
        }
        __syncthreads();
    }
    u64* d = dst + (size_t)batch * N + (size_t)pair * PRE;
    for (int i = threadIdx.x; i < PRE; i += blockDim.x) d[i] = s[i];
}

// ---------------- kernel 4: gather boxes for top-4096, precompute corners/areas ----------------
__global__ void k_gather(const float* __restrict__ boxes) {
    int t = blockIdx.x * blockDim.x + threadIdx.x;
    if (t >= B * PRE) return;
    int b = t >> 12;
    int r = t & (PRE - 1);
    u64 key = g_keysB[(size_t)b * N + r];
    unsigned int n = 0xFFFFFFFFu - (unsigned int)(key & 0xFFFFFFFFu);
    float sc = __uint_as_float((unsigned int)(key >> 32));
    const float* bx = boxes + ((size_t)b * N + n) * 7;
    float x = bx[0], y = bx[1], z = bx[2], dx = bx[3], dy = bx[4], dz = bx[5], hd = bx[6];
    float* ob = g_boxes7 + (size_t)t * 7;
    ob[0] = x; ob[1] = y; ob[2] = z; ob[3] = dx; ob[4] = dy; ob[5] = dz; ob[6] = hd;
    g_x1[t] = x - 0.5f * dx;
    g_x2[t] = x + 0.5f * dx;
    g_y1[t] = y - 0.5f * dy;
    g_y2[t] = y + 0.5f * dy;
    g_area[t] = dx * dy;
    g_sc[t] = sc;
    g_lb[t] = (int)g_labels8[(size_t)b * N + n];
}

// ---------------- kernel 5: parallel suppression mask for top-left M x M ----------------
// mask[b][i][w] bit j set  <=>  col = w*64+j > i  AND  iou(i, col) > TH
__global__ void k_mask() {
    __shared__ float rx1[64], ry1[64], rx2[64], ry2[64], ra[64];
    __shared__ float cx1[512], cy1[512], cx2[512], cy2[512], ca[512];
    int b = blockIdx.y;
    int rowBase = blockIdx.x * 64;
    int tid = threadIdx.x;

    if (tid < 64) {
        int g = b * PRE + rowBase + tid;
        rx1[tid] = g_x1[g]; ry1[tid] = g_y1[g];
        rx2[tid] = g_x2[g]; ry2[tid] = g_y2[g];
        ra[tid] = g_area[g];
    }
    for (int cc = 0; cc < M / 512; cc++) {
        __syncthreads();
        for (int i = tid; i < 512; i += 256) {
            int g = b * PRE + cc * 512 + i;
            cx1[i] = g_x1[g]; cy1[i] = g_y1[g];
            cx2[i] = g_x2[g]; cy2[i] = g_y2[g];
            ca[i] = g_area[g];
        }
        __syncthreads();
        #pragma unroll
        for (int pp = 0; pp < 2; pp++) {
            int p = tid + pp * 256;        // 0..511
            int r = p >> 3;                // 0..63
            int w = p & 7;                 // word within chunk
            int row = rowBase + r;
            float x1 = rx1[r], y1 = ry1[r], x2 = rx2[r], y2 = ry2[r], ai = ra[r];
            u64 bits = 0;
            int cb = w * 64;
            int colBase = cc * 512 + cb;
            #pragma unroll 4
            for (int j = 0; j < 64; j++) {
                float ix = fminf(x2, cx2[cb + j]) - fmaxf(x1, cx1[cb + j]);
                float iy = fminf(y2, cy2[cb + j]) - fmaxf(y1, cy1[cb + j]);
                ix = fmaxf(ix, 0.f);
                iy = fmaxf(iy, 0.f);
                float inter = ix * iy;
                float iou = inter / (ai + ca[cb + j] - inter + 1e-6f);
                if ((colBase + j > row) & (iou > NMS_TH)) bits |= 1ull << j;
            }
            g_mask[((size_t)b * M + row) * W + cc * 8 + w] = bits;
        }
    }
}

// ---------------- kernel 6: warp-per-batch bitwise greedy scan ----------------
__global__ void k_scan() {
    int b = blockIdx.x;
    int t = threadIdx.x;            // 32 threads
    const u64* mask = g_mask + (size_t)b * M * W;
    u64 removed = 0;
    u64 row = mask[t];              // prefetch row 0
    int kept = 0;
    for (int i = 0; i < M; i++) {
        u64 nrow = (i + 1 < M) ? mask[(size_t)(i + 1) * W + t] : 0ull;
        int bitset = (int)((removed >> (i & 63)) & 1ull);
        bitset = __shfl_sync(0xffffffff, bitset, i >> 6);
        if (!bitset) {
            if (t == 0) g_keep[b * POST + kept] = i;
            kept++;
            removed |= row;
            if (kept == POST) break;
        }
        row = nrow;
    }
    if (t == 0) {
        g_cnt[b] = kept;
        g_fail[b] = (kept < POST) ? 1 : 0;
    }
}

// ---------------- kernel 7: emit outputs (fast path) ----------------
__global__ void k_emit(float* __restrict__ out) {
    int t = blockIdx.x * blockDim.x + threadIdx.x;
    if (t >= B * POST) return;
    int b = t / POST, s = t % POST;
    if (g_fail[b]) return;          // fallback will write this batch
    float* rois   = out;
    float* scores = out + B * POST * 7;
    float* labs   = out + B * POST * 7 + B * POST;
    int cnt = g_cnt[b];
    if (s < cnt) {
        int gi = b * PRE + g_keep[b * POST + s];
        const float* bx = g_boxes7 + (size_t)gi * 7;
        #pragma unroll
        for (int q = 0; q < 7; q++) rois[t * 7 + q] = bx[q];
        scores[t] = g_sc[gi];
        labs[t] = (float)(g_lb[gi] + 1);
    } else {
        #pragma unroll
        for (int q = 0; q < 7; q++) rois[t * 7 + q] = 0.f;
        scores[t] = 0.f;
        labs[t] = 0.f;
    }
}

// ---------------- kernel 8: sequential fallback (only when fast path failed) ----------------
#define NMS_THREADS 256
#define NMS_SMEM (5 * PRE * 4 + PRE)

__global__ void k_nms_fallback(float* __restrict__ out) {
    int b = blockIdx.x;
    if (!g_fail[b]) return;
    extern __shared__ float sm[];
    float* sx1 = sm;
    float* sy1 = sm + PRE;
    float* sx2 = sm + 2 * PRE;
    float* sy2 = sm + 3 * PRE;
    float* sar = sm + 4 * PRE;
    unsigned char* sup = (unsigned char*)(sm + 5 * PRE);
    __shared__ int s_i;

    int tid = threadIdx.x;
    int base = b * PRE;

    for (int i = tid; i < PRE; i += NMS_THREADS) {
        sx1[i] = g_x1[base + i];
        sy1[i] = g_y1[base + i];
        sx2[i] = g_x2[base + i];
        sy2[i] = g_y2[base + i];
        sar[i] = g_area[base + i];
        sup[i] = 0;
    }
    float* rois   = out;
    float* scores = out + B * POST * 7;
    float* labs   = out + B * POST * 7 + B * POST;
    for (int i = tid; i < POST * 7; i += NMS_THREADS) rois[b * POST * 7 + i] = 0.f;
    for (int i = tid; i < POST; i += NMS_THREADS) { scores[b * POST + i] = 0.f; labs[b * POST + i] = 0.f; }
    __syncthreads();

    int kept = 0;
    int cursor = 0;
    while (true) {
        if (tid == 0) {
            int i = cursor;
            while (i < PRE && sup[i]) i++;
            s_i = (i < PRE) ? i : -1;
        }
        __syncthreads();
        int i = s_i;
        if (i < 0) break;
        cursor = i + 1;

        if (tid < 7) rois[(b * POST + kept) * 7 + tid] = g_boxes7[(size_t)(base + i) * 7 + tid];
        if (tid == 7) scores[b * POST + kept] = g_sc[base + i];
        if (tid == 8) labs[b * POST + kept] = (float)(g_lb[base + i] + 1);
        kept++;
        if (kept >= POST) break;

        float xi1 = sx1[i], yi1 = sy1[i], xi2 = sx2[i], yi2 = sy2[i], ai = sar[i];
        for (int j = i + 1 + tid; j < PRE; j += NMS_THREADS) {
            if (!sup[j]) {
                float ix = fminf(xi2, sx2[j]) - fmaxf(xi1, sx1[j]);
                float iy = fminf(yi2, sy2[j]) - fmaxf(yi1, sy1[j]);
                ix = fmaxf(ix, 0.f);
                iy = fmaxf(iy, 0.f);
                float inter = ix * iy;
                float iou = inter / (ai + sar[j] - inter + 1e-6f);
                if (iou > NMS_TH) sup[j] = 1;
            }
        }
        __syncthreads();
    }
}

// ---------------- launch ----------------
extern "C" void kernel_launch(void* const* d_in, const int* in_sizes, int n_in,
                              void* d_out, int out_size) {
    const float* boxes = (const float*)d_in[0];
    const float* cls   = (const float*)d_in[1];
    if (in_sizes[0] == B * N * 3) {
        cls = (const float*)d_in[0];
        boxes = (const float*)d_in[1];
    }

    cudaFuncSetAttribute(k_merge, cudaFuncAttributeMaxDynamicSharedMemorySize, 2 * PRE * 8);
    cudaFuncSetAttribute(k_nms_fallback, cudaFuncAttributeMaxDynamicSharedMemorySize, NMS_SMEM);

    k_score<<<(B * N + 255) / 256, 256>>>(cls);
    k_sort4096<<<B * 8, 1024>>>();
    k_merge<<<B * 4, 1024, 2 * PRE * 8>>>(0);
    k_merge<<<B * 2, 1024, 2 * PRE * 8>>>(1);
    k_merge<<<B * 1, 1024, 2 * PRE * 8>>>(2);
    k_gather<<<(B * PRE + 255) / 256, 256>>>(boxes);
    {
        dim3 g(M / 64, B);
        k_mask<<<g, 256>>>();
    }
    k_scan<<<B, 32>>>();
    k_emit<<<(B * POST + 255) / 256, 256>>>((float*)d_out);
    k_nms_fallback<<<B, NMS_THREADS, NMS_SMEM>>>((float*)d_out);
}